// round 6
// baseline (speedup 1.0000x reference)
#include <cuda_runtime.h>
#include <cuda_fp16.h>
#include <cstdint>

// ---------------- problem dims (fixed) ----------------
#define MDIM 8192
#define NDIM 4096
#define KDIM 4096

// ---------------- GEMM tiling ----------------
#define BM 256
#define BN 128
#define BK 64
#define STAGES 4
#define GEMM_THREADS 256
#define GEMM_CTAS 148                 // persistent: one CTA per SM
#define MTILES (MDIM / BM)            // 32
#define NTILES (NDIM / BN)            // 32
#define TOTAL_TILES (MTILES * NTILES) // 1024
#define KTILES (KDIM / BK)            // 64
#define A_STAGE_BYTES (BM * 128)      // 32KB
#define B_STAGE_BYTES (BN * 128)      // 16KB
#define STAGE_BYTES (A_STAGE_BYTES + B_STAGE_BYTES)   // 48KB
#define SMEM_TOTAL (STAGES * STAGE_BYTES)             // 192KB

// fp16 scratch (static device globals; no allocations)
__device__ __half d_Ah[(size_t)MDIM * KDIM];   // 64 MB
__device__ __half d_Wh[(size_t)NDIM * KDIM];   // 32 MB

// ---------------- PTX helpers ----------------
__device__ __forceinline__ uint32_t smem_u32(const void* p) {
    uint32_t a;
    asm("{ .reg .u64 t; cvta.to.shared.u64 t, %1; cvt.u32.u64 %0, t; }" : "=r"(a) : "l"(p));
    return a;
}

__device__ __forceinline__ void cp_async_16(uint32_t smem_dst, const void* gptr) {
    asm volatile("cp.async.cg.shared.global [%0], [%1], 16;"
                 :: "r"(smem_dst), "l"(__cvta_generic_to_global(gptr)) : "memory");
}

#define CP_COMMIT() asm volatile("cp.async.commit_group;" ::: "memory")
#define CP_WAIT(n)  asm volatile("cp.async.wait_group %0;" :: "n"(n) : "memory")

#define LDSM4(r0, r1, r2, r3, addr) \
    asm volatile("ldmatrix.sync.aligned.m8n8.x4.shared.b16 {%0,%1,%2,%3}, [%4];" \
        : "=r"(r0), "=r"(r1), "=r"(r2), "=r"(r3) : "r"(addr))

#define MMA16816(c, a0, a1, a2, a3, b0, b1) \
    asm volatile("mma.sync.aligned.m16n8k16.row.col.f32.f16.f16.f32 " \
        "{%0,%1,%2,%3}, {%4,%5,%6,%7}, {%8,%9}, {%0,%1,%2,%3};" \
        : "+f"((c)[0]), "+f"((c)[1]), "+f"((c)[2]), "+f"((c)[3]) \
        : "r"(a0), "r"(a1), "r"(a2), "r"(a3), "r"(b0), "r"(b1))

// swizzled byte offset within a 128B-row tile: col ^= (row&7)<<4
__device__ __forceinline__ uint32_t swz(int row, int colbyte) {
    return (uint32_t)(row * 128 + (colbyte ^ ((row & 7) << 4)));
}

// ---------------- fused pre-pass (x->fp16 | 4bit->fp16), MLP=4 ----------------
#define PREP_A_BLOCKS 8192
#define PREP_W_BLOCKS 2048
__global__ void prep_kernel(const float* __restrict__ x, const int* __restrict__ qw,
                            const float* __restrict__ sc, const int* __restrict__ qz) {
    const int b = blockIdx.x;
    if (b < PREP_A_BLOCKS) {
        const size_t stride = (size_t)PREP_A_BLOCKS * 256;   // 2097152
        size_t i = (size_t)b * 256 + threadIdx.x;
        const float4* src = reinterpret_cast<const float4*>(x);
        __half2* dst = reinterpret_cast<__half2*>(d_Ah);
        float4 v0 = src[i];
        float4 v1 = src[i + stride];
        float4 v2 = src[i + 2 * stride];
        float4 v3 = src[i + 3 * stride];
        dst[2 * i + 0] = __floats2half2_rn(v0.x, v0.y);
        dst[2 * i + 1] = __floats2half2_rn(v0.z, v0.w);
        dst[2 * (i + stride) + 0] = __floats2half2_rn(v1.x, v1.y);
        dst[2 * (i + stride) + 1] = __floats2half2_rn(v1.z, v1.w);
        dst[2 * (i + 2 * stride) + 0] = __floats2half2_rn(v2.x, v2.y);
        dst[2 * (i + 2 * stride) + 1] = __floats2half2_rn(v2.z, v2.w);
        dst[2 * (i + 3 * stride) + 0] = __floats2half2_rn(v3.x, v3.y);
        dst[2 * (i + 3 * stride) + 1] = __floats2half2_rn(v3.z, v3.w);
    } else {
        const size_t wstride = (size_t)PREP_W_BLOCKS * 256;  // 524288 int4s per pass
        size_t t0 = (size_t)(b - PREP_A_BLOCKS) * 256 + threadIdx.x;
        #pragma unroll
        for (int r = 0; r < 4; r++) {
            size_t t = t0 + r * wstride;
            int4 b4 = reinterpret_cast<const int4*>(qw)[t];
            int g = (int)(t >> 4);               // (t*4 bytes) >> 6 : flat group index
            int zp = qz[g >> 1];
            int z = (g & 1) ? ((zp >> 4) & 15) : (zp & 15);
            float s = sc[g];
            __half2 h[4];
            int bb[4] = {b4.x, b4.y, b4.z, b4.w};
            #pragma unroll
            for (int q = 0; q < 4; q++) {
                float lo = (float)((bb[q] & 15) - z) * s;
                float hi = (float)(((bb[q] >> 4) & 15) - z) * s;
                h[q] = __floats2half2_rn(lo, hi);
            }
            reinterpret_cast<uint4*>(d_Wh)[t] = *reinterpret_cast<uint4*>(h);
        }
    }
}

// ---------------- persistent GEMM (mma.sync m16n8k16, TN, warp tile 64x64) ----------------
__global__ void __launch_bounds__(GEMM_THREADS, 1)
gemm_kernel(const float* __restrict__ bias, float* __restrict__ out) {
    extern __shared__ char smem[];
    const uint32_t sb = smem_u32(smem);
    const int tid = threadIdx.x;
    const int wid = tid >> 5;
    const int lane = tid & 31;
    const int G = gridDim.x;

    // warp layout: 4(M) x 2(N); warp tile 64x64
    const int wm = wid & 3;
    const int wn = wid >> 2;

    // ---- per-lane ldmatrix base addresses (slot 0) ----
    const int lr = lane & 15;
    const int lc = (lane >> 4) * 16;
    uint32_t aA[4], aB[4];
    #pragma unroll
    for (int i = 0; i < 4; i++) {
        aA[i] = sb + swz(wm * 64 + i * 16 + lr, lc);
        aB[i] = sb + (uint32_t)A_STAGE_BYTES + swz(wn * 64 + i * 16 + lr, lc);
    }

    float acc[4][8][4];
    #pragma unroll
    for (int mi = 0; mi < 4; mi++)
        #pragma unroll
        for (int ni = 0; ni < 8; ni++)
            #pragma unroll
            for (int q = 0; q < 4; q++) acc[mi][ni][q] = 0.0f;

    // producer slice p (3 of 12 chunks) for k-chunk pk into stage slot
    auto issue_part = [&](const __half* Ab, const __half* Bb, int pk, int slot, int p) {
        const uint32_t stb = sb + (uint32_t)slot * STAGE_BYTES;
        const int k0 = pk * BK;
        #pragma unroll
        for (int q = 0; q < 3; q++) {
            const int c = tid + (3 * p + q) * 256;
            const int isB = (c >= 2048) ? 1 : 0;
            const int cc = c - isB * 2048;
            const int row = cc >> 3;
            const int j = cc & 7;
            const __half* g = (isB ? Bb : Ab) + (size_t)row * KDIM + k0 + j * 8;
            cp_async_16(stb + (uint32_t)isB * A_STAGE_BYTES + swz(row, j * 16), g);
        }
    };

    uint32_t afr[2][16], bfr[2][16];
    auto load_frags = [&](uint32_t stoff, int kk, int buf) {
        const uint32_t kx = (uint32_t)(kk << 5);
        #pragma unroll
        for (int i = 0; i < 4; i++) {
            LDSM4(afr[buf][i * 4 + 0], afr[buf][i * 4 + 1], afr[buf][i * 4 + 2],
                  afr[buf][i * 4 + 3], (aA[i] + stoff) ^ kx);
            LDSM4(bfr[buf][i * 4 + 0], bfr[buf][i * 4 + 1], bfr[buf][i * 4 + 2],
                  bfr[buf][i * 4 + 3], (aB[i] + stoff) ^ kx);
        }
    };

    auto do_mma = [&](int buf) {
        #pragma unroll
        for (int mi = 0; mi < 4; mi++) {
            #pragma unroll
            for (int t = 0; t < 4; t++) {
                MMA16816(acc[mi][2 * t + 0], afr[buf][mi * 4 + 0], afr[buf][mi * 4 + 1],
                         afr[buf][mi * 4 + 2], afr[buf][mi * 4 + 3],
                         bfr[buf][t * 4 + 0], bfr[buf][t * 4 + 2]);
                MMA16816(acc[mi][2 * t + 1], afr[buf][mi * 4 + 0], afr[buf][mi * 4 + 1],
                         afr[buf][mi * 4 + 2], afr[buf][mi * 4 + 3],
                         bfr[buf][t * 4 + 1], bfr[buf][t * 4 + 3]);
            }
        }
    };

    // ---- producer state (runs dist-3 k-chunks ahead, across tile boundaries) ----
    int ptile = blockIdx.x;
    int pkt = 0;
    const __half* pA = d_Ah + (size_t)(ptile / NTILES) * BM * KDIM;
    const __half* pB = d_Wh + (size_t)(ptile % NTILES) * BN * KDIM;
    bool pvalid = true;

    // prologue: fill slots 0..2 (positions 0..2 of first tile)
    #pragma unroll
    for (int s = 0; s < STAGES - 1; s++) {
        #pragma unroll
        for (int p = 0; p < 4; p++) issue_part(pA, pB, pkt, s, p);
        CP_COMMIT();
        ++pkt;   // first tile has 64 >= 3 k-chunks, no wrap possible
    }
    int pslot = STAGES - 1;

    CP_WAIT(STAGES - 2);
    __syncthreads();
    load_frags(0, 0, 0);
    int cslot = 0;

    const int r = lane >> 2;
    const int cpair = (lane & 3) * 2;

    for (int ctile = blockIdx.x; ctile < TOTAL_TILES; ctile += G) {
        const bool last_tile = (ctile + G >= TOTAL_TILES);
        for (int kt = 0; kt < KTILES; ++kt) {
            const uint32_t stoff = (uint32_t)cslot * STAGE_BYTES;
            #pragma unroll
            for (int kk = 0; kk < 4; kk++) {
                if (pvalid) issue_part(pA, pB, pkt, pslot, kk);
                if (kk < 3) {
                    load_frags(stoff, kk + 1, (kk + 1) & 1);
                } else {
                    CP_COMMIT();
                    CP_WAIT(STAGES - 2);
                }
                do_mma(kk & 1);
            }
            // advance producer one k-chunk (may roll to this CTA's next tile)
            if (++pkt == KTILES) {
                pkt = 0;
                ptile += G;
                pvalid = (ptile < TOTAL_TILES);
                if (pvalid) {
                    pA = d_Ah + (size_t)(ptile / NTILES) * BM * KDIM;
                    pB = d_Wh + (size_t)(ptile % NTILES) * BN * KDIM;
                }
            }
            pslot = (pslot + 1) & 3;
            __syncthreads();
            cslot = (cslot + 1) & 3;
            if (!(last_tile && kt == KTILES - 1))
                load_frags((uint32_t)cslot * STAGE_BYTES, 0, 0);
        }

        // ---- epilogue for ctile: bias + float2 stores; reset acc ----
        {
            const int m0 = (ctile / NTILES) * BM;
            const int n0 = (ctile % NTILES) * BN;
            const int mbase = m0 + wm * 64;
            const int nbase = n0 + wn * 64;
            float bx[8], by[8];
            #pragma unroll
            for (int ni = 0; ni < 8; ni++) {
                bx[ni] = __ldg(&bias[nbase + ni * 8 + cpair]);
                by[ni] = __ldg(&bias[nbase + ni * 8 + cpair + 1]);
            }
            #pragma unroll
            for (int mi = 0; mi < 4; mi++) {
                const int row0 = mbase + mi * 16 + r;
                float* o0 = out + (size_t)row0 * NDIM;
                float* o1 = out + (size_t)(row0 + 8) * NDIM;
                #pragma unroll
                for (int ni = 0; ni < 8; ni++) {
                    const int col = nbase + ni * 8 + cpair;
                    *reinterpret_cast<float2*>(o0 + col) =
                        make_float2(acc[mi][ni][0] + bx[ni], acc[mi][ni][1] + by[ni]);
                    *reinterpret_cast<float2*>(o1 + col) =
                        make_float2(acc[mi][ni][2] + bx[ni], acc[mi][ni][3] + by[ni]);
                    acc[mi][ni][0] = 0.0f; acc[mi][ni][1] = 0.0f;
                    acc[mi][ni][2] = 0.0f; acc[mi][ni][3] = 0.0f;
                }
            }
        }
    }
}

// ---------------- launch ----------------
extern "C" void kernel_launch(void* const* d_in, const int* in_sizes, int n_in,
                              void* d_out, int out_size) {
    const float* x       = (const float*)d_in[0];
    const int*   qweight = (const int*)d_in[1];
    const float* scales  = (const float*)d_in[2];
    const int*   qzeros  = (const int*)d_in[3];
    const float* bias    = (const float*)d_in[4];
    float* out = (float*)d_out;

    prep_kernel<<<PREP_A_BLOCKS + PREP_W_BLOCKS, 256>>>(x, qweight, scales, qzeros);

    cudaFuncSetAttribute(gemm_kernel, cudaFuncAttributeMaxDynamicSharedMemorySize, SMEM_TOTAL);
    gemm_kernel<<<GEMM_CTAS, GEMM_THREADS, SMEM_TOTAL>>>(bias, out);
}